// round 14
// baseline (speedup 1.0000x reference)
#include <cuda_runtime.h>
#include <cuda_fp16.h>
#include <cstdint>

#define N512 512
#define NBATCH 96
#define NN (N512 * N512)
#define NELEM ((size_t)NBATCH * NN)   // 25,165,824

// ---------------- device scratch (no allocations allowed) ----------------
__device__ __half g_Xh[NELEM];          // X quantized fp16
__device__ __half g_tmpH[NELEM];        // stage-1 output (fp16)
__device__ __half g_Th[NN];             // T[k][n]
__device__ __half g_Tth[NN];            // T^T[i][k]

// ---------------- helpers ----------------
__device__ __forceinline__ uint32_t smem_u32(const void* p) {
    uint32_t a;
    asm("{ .reg .u64 t; cvta.to.shared.u64 t, %1; cvt.u32.u64 %0, t; }"
        : "=r"(a) : "l"(p));
    return a;
}

#define LDSM_X4(r0, r1, r2, r3, addr)                                   \
    asm volatile("ldmatrix.sync.aligned.m8n8.x4.shared.b16 "            \
                 "{%0,%1,%2,%3}, [%4];"                                 \
                 : "=r"(r0), "=r"(r1), "=r"(r2), "=r"(r3) : "r"(addr))

#define LDSM_X4T(r0, r1, r2, r3, addr)                                  \
    asm volatile("ldmatrix.sync.aligned.m8n8.x4.trans.shared.b16 "      \
                 "{%0,%1,%2,%3}, [%4];"                                 \
                 : "=r"(r0), "=r"(r1), "=r"(r2), "=r"(r3) : "r"(addr))

#define MMA_F16(c, a, b)                                                \
    asm volatile("mma.sync.aligned.m16n8k16.row.col.f32.f16.f16.f32 "   \
                 "{%0,%1,%2,%3}, {%4,%5,%6,%7}, {%8,%9}, {%0,%1,%2,%3};"\
                 : "+f"((c)[0]), "+f"((c)[1]), "+f"((c)[2]), "+f"((c)[3])\
                 : "r"((a)[0]), "r"((a)[1]), "r"((a)[2]), "r"((a)[3]),  \
                   "r"((b)[0]), "r"((b)[1]))

#define CP_ASYNC16(dst, src)                                            \
    asm volatile("cp.async.cg.shared.global [%0], [%1], 16;"            \
                 :: "r"(dst), "l"(src))
#define CP_COMMIT()  asm volatile("cp.async.commit_group;")
#define CP_WAIT1()   asm volatile("cp.async.wait_group 1;")

// ---------------- merged prep: quant X + build basis ----------------------
__global__ __launch_bounds__(256)
void prep_all(const float4* __restrict__ X, uint2* __restrict__ H,
              __half* __restrict__ Th, __half* __restrict__ Tth) {
    size_t i = (size_t)blockIdx.x * 256 + threadIdx.x;
    if (i < NELEM / 4) {
        float4 v = X[i];
        __half2 p0 = __floats2half2_rn(v.x, v.y);
        __half2 p1 = __floats2half2_rn(v.z, v.w);
        H[i] = make_uint2(*reinterpret_cast<uint32_t*>(&p0),
                          *reinterpret_cast<uint32_t*>(&p1));
    }
    if (i < (size_t)NN) {           // first 1024 blocks also build the basis
        int k = (int)(i >> 9);
        int n = (int)(i & 511);
        float ck = (k == 0) ? rsqrtf(512.0f) : sqrtf(2.0f / 512.0f);
        float v = ck * cospif((float)(k * (2 * n + 1)) * (1.0f / 1024.0f));
        __half h = __float2half_rn(v);
        Th[k * N512 + n]  = h;
        Tth[n * N512 + k] = h;
    }
}

// ---------------- SMEM layout (bytes) ----------------
// BK = 64. A tile: 128 rows x 64 fp16 (128B) pad-> 144B/row = 18432 B
//          B tile:  64 rows x 128 fp16 (256B) pad-> 272B/row = 17408 B
// stage: A | B = 35840 B ; 3 stages = 107520 B  (2 CTAs/SM)
#define A_STRIDE 144
#define B_STRIDE 272
#define A_TILE   18432
#define STAGE_B  35840
#define SMEM_TOTAL (3 * STAGE_B)

// ---------------- GEMM: C = A * B (fp16 in, fp32 acc), single pass --------
// CTA 128x128, BK=64, 8 chunks, 3-stage cp.async, 8 warps, warp tile 64x32.
// B fragments double-buffered across k16 steps.
template <bool STAGE2>
__global__ __launch_bounds__(256, 2)
void gemm1p(const __half* __restrict__ AG,
            const __half* __restrict__ BG,
            __half* __restrict__ OutHalf,
            float* __restrict__ OutF,
            long strideA, long strideB) {
    extern __shared__ __align__(16) char sm[];
    const uint32_t smb = smem_u32(sm);

    const int tid  = threadIdx.x;
    const int lane = tid & 31;
    const int wid  = tid >> 5;
    const int warpM = wid & 1;
    const int warpN = wid >> 1;

    const __half* A = AG + (long)blockIdx.z * strideA;
    const __half* B = BG + (long)blockIdx.z * strideB;

    const int tileM = blockIdx.y * 128;
    const int tileN = blockIdx.x * 128;

    auto issue = [&](int k0, int buf) {
        const uint32_t base = smb + buf * STAGE_B;
        #pragma unroll
        for (int i = 0; i < 4; ++i) {
            int u = tid + i * 256;
            int row = u >> 3;
            int c16 = u & 7;
            uint32_t dst = base + row * A_STRIDE + c16 * 16;
            CP_ASYNC16(dst, &A[(long)(tileM + row) * N512 + k0 + c16 * 8]);
        }
        #pragma unroll
        for (int i = 0; i < 4; ++i) {
            int u = tid + i * 256;
            int row = u >> 4;
            int c16 = u & 15;
            uint32_t dst = base + A_TILE + row * B_STRIDE + c16 * 16;
            CP_ASYNC16(dst, &B[(long)(k0 + row) * N512 + tileN + c16 * 8]);
        }
        CP_COMMIT();
    };

    float acc[4][4][4] = {};

    // ldmatrix lane addressing (bytes, relative to stage base)
    const uint32_t aAddr0 = (uint32_t)((warpM * 64 + (lane & 15)) * A_STRIDE
                                       + (lane >> 4) * 16);
    const uint32_t bAddr0 = (uint32_t)(A_TILE + (lane & 15) * B_STRIDE
                                       + warpN * 64 + (lane >> 4) * 16);

    issue(0, 0);
    issue(64, 1);

    for (int c = 0; c < 8; ++c) {
        const int buf = c % 3;
        CP_WAIT1();
        __syncthreads();
        if (c + 2 < 8) issue((c + 2) * 64, (c + 2) % 3);
        else           CP_COMMIT();          // keep group counting aligned

        const uint32_t sb = smb + buf * STAGE_B;

        // B fragments double-buffered across ks
        uint32_t b_[2][4][2];
        {
            #pragma unroll
            for (int np = 0; np < 2; ++np) {
                uint32_t bd = sb + bAddr0 + np * 32;
                uint32_t t0, t1, t2, t3;
                LDSM_X4T(t0, t1, t2, t3, bd);
                b_[0][2 * np][0] = t0;     b_[0][2 * np][1] = t1;
                b_[0][2 * np + 1][0] = t2; b_[0][2 * np + 1][1] = t3;
            }
        }

        #pragma unroll
        for (int ks = 0; ks < 4; ++ks) {
            const int cur = ks & 1;
            uint32_t a_[4][4];
            #pragma unroll
            for (int mt = 0; mt < 4; ++mt) {
                uint32_t ad = sb + aAddr0 + mt * (16 * A_STRIDE) + ks * 32;
                LDSM_X4(a_[mt][0], a_[mt][1], a_[mt][2], a_[mt][3], ad);
            }
            if (ks < 3) {
                const int nxt = cur ^ 1;
                #pragma unroll
                for (int np = 0; np < 2; ++np) {
                    uint32_t bd = sb + bAddr0 + (ks + 1) * (16 * B_STRIDE) + np * 32;
                    uint32_t t0, t1, t2, t3;
                    LDSM_X4T(t0, t1, t2, t3, bd);
                    b_[nxt][2 * np][0] = t0;     b_[nxt][2 * np][1] = t1;
                    b_[nxt][2 * np + 1][0] = t2; b_[nxt][2 * np + 1][1] = t3;
                }
            }
            #pragma unroll
            for (int mt = 0; mt < 4; ++mt)
                #pragma unroll
                for (int nt = 0; nt < 4; ++nt)
                    MMA_F16(acc[mt][nt], a_[mt], b_[cur][nt]);
        }
    }

    // ---------------- epilogue ----------------
    const long imgC = (long)blockIdx.z * NN;
    #pragma unroll
    for (int mt = 0; mt < 4; ++mt) {
        int r0 = tileM + warpM * 64 + mt * 16 + (lane >> 2);
        #pragma unroll
        for (int nt = 0; nt < 4; ++nt) {
            int c0 = tileN + warpN * 32 + nt * 8 + (lane & 3) * 2;
            if (!STAGE2) {
                __half2 p0 = __floats2half2_rn(acc[mt][nt][0], acc[mt][nt][1]);
                __half2 p1 = __floats2half2_rn(acc[mt][nt][2], acc[mt][nt][3]);
                *reinterpret_cast<__half2*>(&OutHalf[imgC + (long)r0 * N512 + c0]) = p0;
                *reinterpret_cast<__half2*>(&OutHalf[imgC + (long)(r0 + 8) * N512 + c0]) = p1;
            } else {
                *reinterpret_cast<float2*>(&OutF[imgC + (long)r0 * N512 + c0]) =
                    make_float2(acc[mt][nt][0], acc[mt][nt][1]);
                *reinterpret_cast<float2*>(&OutF[imgC + (long)(r0 + 8) * N512 + c0]) =
                    make_float2(acc[mt][nt][2], acc[mt][nt][3]);
            }
        }
    }
}

// ---------------- host launcher ----------------
extern "C" void kernel_launch(void* const* d_in, const int* in_sizes, int n_in,
                              void* d_out, int out_size) {
    const float* X = (const float*)d_in[0];
    float* out = (float*)d_out;

    __half *pXh, *pTmpH, *pTh, *pTth;
    cudaGetSymbolAddress((void**)&pXh,   g_Xh);
    cudaGetSymbolAddress((void**)&pTmpH, g_tmpH);
    cudaGetSymbolAddress((void**)&pTh,   g_Th);
    cudaGetSymbolAddress((void**)&pTth,  g_Tth);

    cudaFuncSetAttribute(gemm1p<false>, cudaFuncAttributeMaxDynamicSharedMemorySize, SMEM_TOTAL);
    cudaFuncSetAttribute(gemm1p<true>,  cudaFuncAttributeMaxDynamicSharedMemorySize, SMEM_TOTAL);

    prep_all<<<(int)(NELEM / 4 / 256), 256>>>((const float4*)X, (uint2*)pXh,
                                              pTh, pTth);

    dim3 grid(4, 4, NBATCH);
    // stage 1: C1 = X_h @ T_h   (fp16 intermediate)
    gemm1p<false><<<grid, 256, SMEM_TOTAL>>>(pXh, pTh, pTmpH, nullptr,
                                             (long)NN, 0L);
    // stage 2: Out = Tt_h @ C1  (fp32 output)
    gemm1p<true><<<grid, 256, SMEM_TOTAL>>>(pTth, pTmpH, nullptr, out,
                                            0L, (long)NN);
}

// round 15
// speedup vs baseline: 1.0348x; 1.0348x over previous
#include <cuda_runtime.h>
#include <cuda_fp16.h>
#include <cstdint>

#define N512 512
#define NBATCH 96
#define NN (N512 * N512)
#define NELEM ((size_t)NBATCH * NN)   // 25,165,824

// ---------------- device scratch (no allocations allowed) ----------------
__device__ __half g_tmpH[NELEM];        // stage-1 output (fp16)
__device__ __half g_Th[NN];             // T[k][n]
__device__ __half g_Tth[NN];            // T^T[i][k]

// ---------------- helpers ----------------
__device__ __forceinline__ uint32_t smem_u32(const void* p) {
    uint32_t a;
    asm("{ .reg .u64 t; cvta.to.shared.u64 t, %1; cvt.u32.u64 %0, t; }"
        : "=r"(a) : "l"(p));
    return a;
}

#define LDSM_X4(r0, r1, r2, r3, addr)                                   \
    asm volatile("ldmatrix.sync.aligned.m8n8.x4.shared.b16 "            \
                 "{%0,%1,%2,%3}, [%4];"                                 \
                 : "=r"(r0), "=r"(r1), "=r"(r2), "=r"(r3) : "r"(addr))

#define LDSM_X4T(r0, r1, r2, r3, addr)                                  \
    asm volatile("ldmatrix.sync.aligned.m8n8.x4.trans.shared.b16 "      \
                 "{%0,%1,%2,%3}, [%4];"                                 \
                 : "=r"(r0), "=r"(r1), "=r"(r2), "=r"(r3) : "r"(addr))

#define MMA_F16(c, a, b)                                                \
    asm volatile("mma.sync.aligned.m16n8k16.row.col.f32.f16.f16.f32 "   \
                 "{%0,%1,%2,%3}, {%4,%5,%6,%7}, {%8,%9}, {%0,%1,%2,%3};"\
                 : "+f"((c)[0]), "+f"((c)[1]), "+f"((c)[2]), "+f"((c)[3])\
                 : "r"((a)[0]), "r"((a)[1]), "r"((a)[2]), "r"((a)[3]),  \
                   "r"((b)[0]), "r"((b)[1]))

#define CP_ASYNC16(dst, src)                                            \
    asm volatile("cp.async.cg.shared.global [%0], [%1], 16;"            \
                 :: "r"(dst), "l"(src))
#define CP_COMMIT()  asm volatile("cp.async.commit_group;")
#define CP_WAIT1()   asm volatile("cp.async.wait_group 1;")

// ---------------- basis build ----------------
__global__ void build_basis(__half* __restrict__ Th, __half* __restrict__ Tth) {
    int k = blockIdx.x, n = threadIdx.x;
    float ck = (k == 0) ? rsqrtf(512.0f) : sqrtf(2.0f / 512.0f);
    float v = ck * cospif((float)(k * (2 * n + 1)) * (1.0f / 1024.0f));
    __half h = __float2half_rn(v);
    Th[k * N512 + n]  = h;
    Tth[n * N512 + k] = h;
}

// ============================================================================
// Stage 1 (fused quant): C1 = fp16(X) @ T, X read as fp32 and converted inline
// CTA 128x128, BK=32, 16 chunks. A: LDG fp32 -> cvt -> STS fp16 (2 buffers).
// B: cp.async fp16 (3-stage ring). 8 warps, warp tile 64x32.
// ============================================================================
#define A1_STRIDE 80
#define A1_TILE   10240            // 128 * 80
#define B1_STRIDE 272
#define B1_TILE   8704             // 32 * 272
#define S1_SMEM   (2 * A1_TILE + 3 * B1_TILE)   // 46592 B

__global__ __launch_bounds__(256, 2)
void gemm_s1(const float* __restrict__ X,
             const __half* __restrict__ T,
             __half* __restrict__ Out) {
    extern __shared__ __align__(16) char sm[];
    const uint32_t smb = smem_u32(sm);

    const int tid  = threadIdx.x;
    const int lane = tid & 31;
    const int wid  = tid >> 5;
    const int warpM = wid & 1;
    const int warpN = wid >> 1;

    const long img = (long)blockIdx.z * NN;
    const int tileM = blockIdx.y * 128;
    const int tileN = blockIdx.x * 128;

    // A staging registers: 4 float4 per thread per chunk
    float4 ra[4];
    auto ldgA = [&](int k0) {
        #pragma unroll
        for (int i = 0; i < 4; ++i) {
            int u = tid + i * 256;
            int row = u >> 3;          // 0..127
            int f4  = u & 7;           // 0..7
            ra[i] = *reinterpret_cast<const float4*>(
                &X[img + (long)(tileM + row) * N512 + k0 + f4 * 4]);
        }
    };
    auto stsA = [&](int buf) {
        const uint32_t base = smb + buf * A1_TILE;
        #pragma unroll
        for (int i = 0; i < 4; ++i) {
            int u = tid + i * 256;
            int row = u >> 3;
            int f4  = u & 7;
            __half2 p0 = __floats2half2_rn(ra[i].x, ra[i].y);
            __half2 p1 = __floats2half2_rn(ra[i].z, ra[i].w);
            *reinterpret_cast<uint2*>(sm + (base - smb) + row * A1_STRIDE + f4 * 8) =
                make_uint2(*reinterpret_cast<uint32_t*>(&p0),
                           *reinterpret_cast<uint32_t*>(&p1));
        }
    };
    auto issueB = [&](int k0, int buf) {
        const uint32_t base = smb + 2 * A1_TILE + buf * B1_TILE;
        // 32 rows x 256B = 512 x 16B units, 2 per thread
        #pragma unroll
        for (int i = 0; i < 2; ++i) {
            int u = tid + i * 256;
            int row = u >> 4;
            int c16 = u & 15;
            uint32_t dst = base + row * B1_STRIDE + c16 * 16;
            CP_ASYNC16(dst, &T[(long)(k0 + row) * N512 + tileN + c16 * 8]);
        }
        CP_COMMIT();
    };

    float acc[4][4][4] = {};

    const uint32_t aAddr0 = (uint32_t)((warpM * 64 + (lane & 15)) * A1_STRIDE
                                       + (lane >> 4) * 16);
    const uint32_t bAddr0 = (uint32_t)(2 * A1_TILE + (lane & 15) * B1_STRIDE
                                       + warpN * 64 + (lane >> 4) * 16);

    ldgA(0);
    issueB(0, 0);
    issueB(32, 1);

    for (int c = 0; c < 16; ++c) {
        CP_WAIT1();
        stsA(c & 1);
        __syncthreads();
        if (c + 2 < 16) issueB((c + 2) * 32, (c + 2) % 3);
        else            CP_COMMIT();
        if (c + 1 < 16) ldgA((c + 1) * 32);

        const uint32_t sa = smb + (c & 1) * A1_TILE;
        const uint32_t sb = smb + (c % 3) * B1_TILE;   // rel to B base below

        #pragma unroll
        for (int ks = 0; ks < 2; ++ks) {
            uint32_t a_[4][4], b_[4][2];
            #pragma unroll
            for (int mt = 0; mt < 4; ++mt) {
                uint32_t ad = sa + aAddr0 + mt * (16 * A1_STRIDE) + ks * 32;
                LDSM_X4(a_[mt][0], a_[mt][1], a_[mt][2], a_[mt][3], ad);
            }
            #pragma unroll
            for (int np = 0; np < 2; ++np) {
                uint32_t bd = smb + (c % 3) * B1_TILE + bAddr0
                            + ks * (16 * B1_STRIDE) + np * 32;
                uint32_t t0, t1, t2, t3;
                LDSM_X4T(t0, t1, t2, t3, bd);
                b_[2 * np][0] = t0;     b_[2 * np][1] = t1;
                b_[2 * np + 1][0] = t2; b_[2 * np + 1][1] = t3;
            }
            #pragma unroll
            for (int mt = 0; mt < 4; ++mt)
                #pragma unroll
                for (int nt = 0; nt < 4; ++nt)
                    MMA_F16(acc[mt][nt], a_[mt], b_[nt]);
        }
        __syncthreads();
    }

    // epilogue: fp16 intermediate
    #pragma unroll
    for (int mt = 0; mt < 4; ++mt) {
        int r0 = tileM + warpM * 64 + mt * 16 + (lane >> 2);
        #pragma unroll
        for (int nt = 0; nt < 4; ++nt) {
            int c0 = tileN + warpN * 32 + nt * 8 + (lane & 3) * 2;
            __half2 p0 = __floats2half2_rn(acc[mt][nt][0], acc[mt][nt][1]);
            __half2 p1 = __floats2half2_rn(acc[mt][nt][2], acc[mt][nt][3]);
            *reinterpret_cast<__half2*>(&Out[img + (long)r0 * N512 + c0]) = p0;
            *reinterpret_cast<__half2*>(&Out[img + (long)(r0 + 8) * N512 + c0]) = p1;
        }
    }
}

// ============================================================================
// Stage 2: Out = Tt @ C1 (both fp16, fp32 out). R12-proven schedule:
// CTA 128x128, BK=64, 8 chunks, 3-stage cp.async, single-buffered fragments.
// ============================================================================
#define A_STRIDE 144
#define B_STRIDE 272
#define A_TILE   18432
#define STAGE_B  35840
#define S2_SMEM  (3 * STAGE_B)

__global__ __launch_bounds__(256, 2)
void gemm_s2(const __half* __restrict__ AG,
             const __half* __restrict__ BG,
             float* __restrict__ OutF) {
    extern __shared__ __align__(16) char sm[];
    const uint32_t smb = smem_u32(sm);

    const int tid  = threadIdx.x;
    const int lane = tid & 31;
    const int wid  = tid >> 5;
    const int warpM = wid & 1;
    const int warpN = wid >> 1;

    const __half* A = AG;                                  // Tt broadcast
    const __half* B = BG + (long)blockIdx.z * NN;          // C1 batched

    const int tileM = blockIdx.y * 128;
    const int tileN = blockIdx.x * 128;

    auto issue = [&](int k0, int buf) {
        const uint32_t base = smb + buf * STAGE_B;
        #pragma unroll
        for (int i = 0; i < 4; ++i) {
            int u = tid + i * 256;
            int row = u >> 3;
            int c16 = u & 7;
            uint32_t dst = base + row * A_STRIDE + c16 * 16;
            CP_ASYNC16(dst, &A[(long)(tileM + row) * N512 + k0 + c16 * 8]);
        }
        #pragma unroll
        for (int i = 0; i < 4; ++i) {
            int u = tid + i * 256;
            int row = u >> 4;
            int c16 = u & 15;
            uint32_t dst = base + A_TILE + row * B_STRIDE + c16 * 16;
            CP_ASYNC16(dst, &B[(long)(k0 + row) * N512 + tileN + c16 * 8]);
        }
        CP_COMMIT();
    };

    float acc[4][4][4] = {};

    const uint32_t aAddr0 = (uint32_t)((warpM * 64 + (lane & 15)) * A_STRIDE
                                       + (lane >> 4) * 16);
    const uint32_t bAddr0 = (uint32_t)(A_TILE + (lane & 15) * B_STRIDE
                                       + warpN * 64 + (lane >> 4) * 16);

    issue(0, 0);
    issue(64, 1);

    for (int c = 0; c < 8; ++c) {
        const int buf = c % 3;
        CP_WAIT1();
        __syncthreads();
        if (c + 2 < 8) issue((c + 2) * 64, (c + 2) % 3);
        else           CP_COMMIT();

        const uint32_t sb = smb + buf * STAGE_B;

        #pragma unroll
        for (int ks = 0; ks < 4; ++ks) {
            uint32_t a_[4][4], b_[4][2];
            #pragma unroll
            for (int mt = 0; mt < 4; ++mt) {
                uint32_t ad = sb + aAddr0 + mt * (16 * A_STRIDE) + ks * 32;
                LDSM_X4(a_[mt][0], a_[mt][1], a_[mt][2], a_[mt][3], ad);
            }
            #pragma unroll
            for (int np = 0; np < 2; ++np) {
                uint32_t bd = sb + bAddr0 + ks * (16 * B_STRIDE) + np * 32;
                uint32_t t0, t1, t2, t3;
                LDSM_X4T(t0, t1, t2, t3, bd);
                b_[2 * np][0] = t0;     b_[2 * np][1] = t1;
                b_[2 * np + 1][0] = t2; b_[2 * np + 1][1] = t3;
            }
            #pragma unroll
            for (int mt = 0; mt < 4; ++mt)
                #pragma unroll
                for (int nt = 0; nt < 4; ++nt)
                    MMA_F16(acc[mt][nt], a_[mt], b_[nt]);
        }
    }

    const long imgC = (long)blockIdx.z * NN;
    #pragma unroll
    for (int mt = 0; mt < 4; ++mt) {
        int r0 = tileM + warpM * 64 + mt * 16 + (lane >> 2);
        #pragma unroll
        for (int nt = 0; nt < 4; ++nt) {
            int c0 = tileN + warpN * 32 + nt * 8 + (lane & 3) * 2;
            *reinterpret_cast<float2*>(&OutF[imgC + (long)r0 * N512 + c0]) =
                make_float2(acc[mt][nt][0], acc[mt][nt][1]);
            *reinterpret_cast<float2*>(&OutF[imgC + (long)(r0 + 8) * N512 + c0]) =
                make_float2(acc[mt][nt][2], acc[mt][nt][3]);
        }
    }
}

// ---------------- host launcher ----------------
extern "C" void kernel_launch(void* const* d_in, const int* in_sizes, int n_in,
                              void* d_out, int out_size) {
    const float* X = (const float*)d_in[0];
    float* out = (float*)d_out;

    __half *pTmpH, *pTh, *pTth;
    cudaGetSymbolAddress((void**)&pTmpH, g_tmpH);
    cudaGetSymbolAddress((void**)&pTh,   g_Th);
    cudaGetSymbolAddress((void**)&pTth,  g_Tth);

    cudaFuncSetAttribute(gemm_s1, cudaFuncAttributeMaxDynamicSharedMemorySize, S1_SMEM);
    cudaFuncSetAttribute(gemm_s2, cudaFuncAttributeMaxDynamicSharedMemorySize, S2_SMEM);

    build_basis<<<N512, N512>>>(pTh, pTth);

    dim3 grid(4, 4, NBATCH);
    // stage 1: C1 = fp16(X) @ T   (quantization fused into A load)
    gemm_s1<<<grid, 256, S1_SMEM>>>(X, pTh, pTmpH);
    // stage 2: Out = Tt @ C1      (fp32 output)
    gemm_s2<<<grid, 256, S2_SMEM>>>(pTth, pTmpH, out);
}

// round 16
// speedup vs baseline: 1.0563x; 1.0208x over previous
#include <cuda_runtime.h>
#include <cuda_fp16.h>
#include <cstdint>

#define N512 512
#define NBATCH 96
#define NN (N512 * N512)
#define NELEM ((size_t)NBATCH * NN)   // 25,165,824

// ---------------- device scratch (no allocations allowed) ----------------
__device__ __half g_Xh[NELEM];          // X cast to fp16
__device__ __half g_Dd[NELEM];          // intermediate, column-deinterleaved
__device__ __half g_Tte[256 * 256];     // Tt[i][2h']   (i rows, h' cols)
__device__ __half g_Tto[256 * 256];     // Tt[i][2h'+1]
__device__ __half g_Tre[256 * 256];     // T[2w'][n]    (w' rows, n cols)
__device__ __half g_Tro[256 * 256];     // T[2w'+1][n]

// ---------------- helpers ----------------
__device__ __forceinline__ uint32_t smem_u32(const void* p) {
    uint32_t a;
    asm("{ .reg .u64 t; cvta.to.shared.u64 t, %1; cvt.u32.u64 %0, t; }"
        : "=r"(a) : "l"(p));
    return a;
}

#define LDSM_X4(r0, r1, r2, r3, addr)                                   \
    asm volatile("ldmatrix.sync.aligned.m8n8.x4.shared.b16 "            \
                 "{%0,%1,%2,%3}, [%4];"                                 \
                 : "=r"(r0), "=r"(r1), "=r"(r2), "=r"(r3) : "r"(addr))

#define LDSM_X4T(r0, r1, r2, r3, addr)                                  \
    asm volatile("ldmatrix.sync.aligned.m8n8.x4.trans.shared.b16 "      \
                 "{%0,%1,%2,%3}, [%4];"                                 \
                 : "=r"(r0), "=r"(r1), "=r"(r2), "=r"(r3) : "r"(addr))

#define MMA_F16(c, a, b)                                                \
    asm volatile("mma.sync.aligned.m16n8k16.row.col.f32.f16.f16.f32 "   \
                 "{%0,%1,%2,%3}, {%4,%5,%6,%7}, {%8,%9}, {%0,%1,%2,%3};"\
                 : "+f"((c)[0]), "+f"((c)[1]), "+f"((c)[2]), "+f"((c)[3])\
                 : "r"((a)[0]), "r"((a)[1]), "r"((a)[2]), "r"((a)[3]),  \
                   "r"((b)[0]), "r"((b)[1]))

#define CP_ASYNC16(dst, src)                                            \
    asm volatile("cp.async.cg.shared.global [%0], [%1], 16;"            \
                 :: "r"(dst), "l"(src))
#define CP_COMMIT()  asm volatile("cp.async.commit_group;")
#define CP_WAIT1()   asm volatile("cp.async.wait_group 1;")

// ---------------- prep kernels ----------------
__global__ __launch_bounds__(256)
void quant_X(const float4* __restrict__ X, uint2* __restrict__ H) {
    size_t i = (size_t)blockIdx.x * 256 + threadIdx.x;
    if (i >= NELEM / 4) return;
    float4 v = X[i];
    __half2 p0 = __floats2half2_rn(v.x, v.y);
    __half2 p1 = __floats2half2_rn(v.z, v.w);
    H[i] = make_uint2(*reinterpret_cast<uint32_t*>(&p0),
                      *reinterpret_cast<uint32_t*>(&p1));
}

// T[k][n] = c_k cos(pi k (2n+1)/1024). Thread (hp = k/2, i = spatial index).
__global__ void build_basis(__half* __restrict__ Tte, __half* __restrict__ Tto,
                            __half* __restrict__ Tre, __half* __restrict__ Tro) {
    int hp = blockIdx.x, i = threadIdx.x;          // hp, i in [0,256)
    float cke = (hp == 0) ? rsqrtf(512.0f) : sqrtf(2.0f / 512.0f);
    float cko = sqrtf(2.0f / 512.0f);
    float ve = cke * cospif((float)(2 * hp * (2 * i + 1)) * (1.0f / 1024.0f));
    float vo = cko * cospif((float)((2 * hp + 1) * (2 * i + 1)) * (1.0f / 1024.0f));
    __half he = __float2half_rn(ve);
    __half ho = __float2half_rn(vo);
    Tte[i * 256 + hp] = he;    // Tt[i][2hp]   (K-contiguous for A operand)
    Tto[i * 256 + hp] = ho;
    Tre[hp * 256 + i] = he;    // T[2hp][n=i]  (N-contiguous for B operand)
    Tro[hp * 256 + i] = ho;
}

// ---------------- SMEM layout (bytes) ----------------
// BK = 32 (in parity-index space). Per stage:
//   A even/odd: 128 rows x 32 fp16 (64B) pad->80B  = 10240 B each
//   B even/odd:  32 rows x 64 fp16 (128B) pad->144B =  4608 B each
#define AS 80
#define AT 10240
#define BS 144
#define BT 4608
#define STG (2 * AT + 2 * BT)       // 29696
#define SMEMT (3 * STG)             // 89088  -> 2 CTAs/SM

// ============================================================================
// Stage 1: D = Tt @ X with parity over h (source height).
//   E[i][w] = sum_h' Tte[i][h'] * X[2h'][w];  O likewise with odd rows.
//   D[i] = E+O ; D[511-i] = E-O  (i in [0,256)).
//   D written column-deinterleaved: col w -> (w>>1) + (w&1)*256.
// CTA: 128 i x 64 w. Grid (8 w-tiles, 2 i-tiles, 96 images).
// ============================================================================
__global__ __launch_bounds__(256, 2)
void gemm_s1(const __half* __restrict__ Xh,
             const __half* __restrict__ Tte, const __half* __restrict__ Tto,
             __half* __restrict__ Dd) {
    extern __shared__ __align__(16) char sm[];
    const uint32_t smb = smem_u32(sm);

    const int tid  = threadIdx.x;
    const int lane = tid & 31;
    const int wid  = tid >> 5;
    const int warpM = wid & 1;      // 64-row slab of i
    const int warpN = wid >> 1;     // 16-col slab of w

    const long img = (long)blockIdx.z * NN;
    const int w0  = blockIdx.x * 64;
    const int it0 = blockIdx.y * 128;

    auto issue = [&](int c, int buf) {
        const uint32_t base = smb + buf * STG;
        const int k0 = c * 32;
        // A tiles (Tte/Tto): 128 rows x 64B = 512 x 16B units, 2/thread each
        #pragma unroll
        for (int i = 0; i < 2; ++i) {
            int u = tid + i * 256;
            int row = u >> 2;
            int c16 = u & 3;
            uint32_t dst = base + row * AS + c16 * 16;
            long g = (long)(it0 + row) * 256 + k0 + c16 * 8;
            CP_ASYNC16(dst,      &Tte[g]);
            CP_ASYNC16(dst + AT, &Tto[g]);
        }
        // B tiles (X rows by parity): 32 rows x 128B = 256 units, 1/thread
        {
            int row = tid >> 3;
            int c16 = tid & 7;
            uint32_t dst = base + 2 * AT + row * BS + c16 * 16;
            long ge = img + (long)(2 * (k0 + row)) * N512 + w0 + c16 * 8;
            CP_ASYNC16(dst,      &Xh[ge]);
            CP_ASYNC16(dst + BT, &Xh[ge + N512]);   // odd row
        }
        CP_COMMIT();
    };

    float accE[4][2][4] = {};
    float accO[4][2][4] = {};

    const uint32_t aAddr0 = (uint32_t)((warpM * 64 + (lane & 15)) * AS
                                       + (lane >> 4) * 16);
    const uint32_t bAddr0 = (uint32_t)(2 * AT + (lane & 15) * BS
                                       + warpN * 32 + (lane >> 4) * 16);

    issue(0, 0);
    issue(1, 1);

    for (int c = 0; c < 8; ++c) {
        const int buf = c % 3;
        CP_WAIT1();
        __syncthreads();
        if (c + 2 < 8) issue(c + 2, (c + 2) % 3);
        else           CP_COMMIT();

        const uint32_t sb = smb + buf * STG;

        #pragma unroll
        for (int ks = 0; ks < 2; ++ks) {
            uint32_t a_[4][4], b_[2][2];
            // ---- even pass ----
            #pragma unroll
            for (int mt = 0; mt < 4; ++mt)
                LDSM_X4(a_[mt][0], a_[mt][1], a_[mt][2], a_[mt][3],
                        sb + aAddr0 + mt * (16 * AS) + ks * 32);
            {
                uint32_t t0, t1, t2, t3;
                LDSM_X4T(t0, t1, t2, t3, sb + bAddr0 + ks * (16 * BS));
                b_[0][0] = t0; b_[0][1] = t1; b_[1][0] = t2; b_[1][1] = t3;
            }
            #pragma unroll
            for (int mt = 0; mt < 4; ++mt)
                #pragma unroll
                for (int nt = 0; nt < 2; ++nt)
                    MMA_F16(accE[mt][nt], a_[mt], b_[nt]);
            // ---- odd pass ----
            #pragma unroll
            for (int mt = 0; mt < 4; ++mt)
                LDSM_X4(a_[mt][0], a_[mt][1], a_[mt][2], a_[mt][3],
                        sb + AT + aAddr0 + mt * (16 * AS) + ks * 32);
            {
                uint32_t t0, t1, t2, t3;
                LDSM_X4T(t0, t1, t2, t3, sb + BT + bAddr0 + ks * (16 * BS));
                b_[0][0] = t0; b_[0][1] = t1; b_[1][0] = t2; b_[1][1] = t3;
            }
            #pragma unroll
            for (int mt = 0; mt < 4; ++mt)
                #pragma unroll
                for (int nt = 0; nt < 2; ++nt)
                    MMA_F16(accO[mt][nt], a_[mt], b_[nt]);
        }
    }

    // epilogue: butterfly over rows, deinterleave columns
    #pragma unroll
    for (int mt = 0; mt < 4; ++mt) {
        int r = it0 + warpM * 64 + mt * 16 + (lane >> 2);
        #pragma unroll
        for (int nt = 0; nt < 2; ++nt) {
            int c0 = w0 + warpN * 16 + nt * 8 + (lane & 3) * 2;   // even
            int cL = c0 >> 1;
            float e, o;
            // (r, c0)
            e = accE[mt][nt][0]; o = accO[mt][nt][0];
            Dd[img + (long)r * N512 + cL]         = __float2half_rn(e + o);
            Dd[img + (long)(511 - r) * N512 + cL] = __float2half_rn(e - o);
            // (r, c0+1)  -> right half
            e = accE[mt][nt][1]; o = accO[mt][nt][1];
            Dd[img + (long)r * N512 + 256 + cL]         = __float2half_rn(e + o);
            Dd[img + (long)(511 - r) * N512 + 256 + cL] = __float2half_rn(e - o);
            // (r+8, c0)
            e = accE[mt][nt][2]; o = accO[mt][nt][2];
            Dd[img + (long)(r + 8) * N512 + cL]   = __float2half_rn(e + o);
            Dd[img + (long)(503 - r) * N512 + cL] = __float2half_rn(e - o);
            // (r+8, c0+1)
            e = accE[mt][nt][3]; o = accO[mt][nt][3];
            Dd[img + (long)(r + 8) * N512 + 256 + cL]   = __float2half_rn(e + o);
            Dd[img + (long)(503 - r) * N512 + 256 + cL] = __float2half_rn(e - o);
        }
    }
}

// ============================================================================
// Stage 2: Out = D @ T with parity over w.
//   E[i][n] = sum_w' Dd[i][w'] * Tre[w'][n];  O with right half / Tro.
//   Out[i][n] = E+O ; Out[i][511-n] = E-O  (n in [0,256)).
// CTA: 128 i x 64 n. Grid (4 n-tiles, 4 i-tiles, 96 images).
// ============================================================================
__global__ __launch_bounds__(256, 2)
void gemm_s2(const __half* __restrict__ Dd,
             const __half* __restrict__ Tre, const __half* __restrict__ Tro,
             float* __restrict__ Out) {
    extern __shared__ __align__(16) char sm[];
    const uint32_t smb = smem_u32(sm);

    const int tid  = threadIdx.x;
    const int lane = tid & 31;
    const int wid  = tid >> 5;
    const int warpM = wid & 1;
    const int warpN = wid >> 1;

    const long img = (long)blockIdx.z * NN;
    const int n0  = blockIdx.x * 64;
    const int it0 = blockIdx.y * 128;

    auto issue = [&](int c, int buf) {
        const uint32_t base = smb + buf * STG;
        const int k0 = c * 32;
        // A tiles (Dd halves): 128 rows x 64B = 512 units, 2/thread each
        #pragma unroll
        for (int i = 0; i < 2; ++i) {
            int u = tid + i * 256;
            int row = u >> 2;
            int c16 = u & 3;
            uint32_t dst = base + row * AS + c16 * 16;
            long g = img + (long)(it0 + row) * N512 + k0 + c16 * 8;
            CP_ASYNC16(dst,      &Dd[g]);          // even half (cols [0,256))
            CP_ASYNC16(dst + AT, &Dd[g + 256]);    // odd half
        }
        // B tiles (Tre/Tro): 32 rows x 128B = 256 units, 1/thread
        {
            int row = tid >> 3;
            int c16 = tid & 7;
            uint32_t dst = base + 2 * AT + row * BS + c16 * 16;
            long g = (long)(k0 + row) * 256 + n0 + c16 * 8;
            CP_ASYNC16(dst,      &Tre[g]);
            CP_ASYNC16(dst + BT, &Tro[g]);
        }
        CP_COMMIT();
    };

    float accE[4][2][4] = {};
    float accO[4][2][4] = {};

    const uint32_t aAddr0 = (uint32_t)((warpM * 64 + (lane & 15)) * AS
                                       + (lane >> 4) * 16);
    const uint32_t bAddr0 = (uint32_t)(2 * AT + (lane & 15) * BS
                                       + warpN * 32 + (lane >> 4) * 16);

    issue(0, 0);
    issue(1, 1);

    for (int c = 0; c < 8; ++c) {
        const int buf = c % 3;
        CP_WAIT1();
        __syncthreads();
        if (c + 2 < 8) issue(c + 2, (c + 2) % 3);
        else           CP_COMMIT();

        const uint32_t sb = smb + buf * STG;

        #pragma unroll
        for (int ks = 0; ks < 2; ++ks) {
            uint32_t a_[4][4], b_[2][2];
            // ---- even pass ----
            #pragma unroll
            for (int mt = 0; mt < 4; ++mt)
                LDSM_X4(a_[mt][0], a_[mt][1], a_[mt][2], a_[mt][3],
                        sb + aAddr0 + mt * (16 * AS) + ks * 32);
            {
                uint32_t t0, t1, t2, t3;
                LDSM_X4T(t0, t1, t2, t3, sb + bAddr0 + ks * (16 * BS));
                b_[0][0] = t0; b_[0][1] = t1; b_[1][0] = t2; b_[1][1] = t3;
            }
            #pragma unroll
            for (int mt = 0; mt < 4; ++mt)
                #pragma unroll
                for (int nt = 0; nt < 2; ++nt)
                    MMA_F16(accE[mt][nt], a_[mt], b_[nt]);
            // ---- odd pass ----
            #pragma unroll
            for (int mt = 0; mt < 4; ++mt)
                LDSM_X4(a_[mt][0], a_[mt][1], a_[mt][2], a_[mt][3],
                        sb + AT + aAddr0 + mt * (16 * AS) + ks * 32);
            {
                uint32_t t0, t1, t2, t3;
                LDSM_X4T(t0, t1, t2, t3, sb + BT + bAddr0 + ks * (16 * BS));
                b_[0][0] = t0; b_[0][1] = t1; b_[1][0] = t2; b_[1][1] = t3;
            }
            #pragma unroll
            for (int mt = 0; mt < 4; ++mt)
                #pragma unroll
                for (int nt = 0; nt < 2; ++nt)
                    MMA_F16(accO[mt][nt], a_[mt], b_[nt]);
        }
    }

    // epilogue: butterfly over columns (n, 511-n), fp32 float2 stores
    #pragma unroll
    for (int mt = 0; mt < 4; ++mt) {
        int r = it0 + warpM * 64 + mt * 16 + (lane >> 2);
        #pragma unroll
        for (int nt = 0; nt < 2; ++nt) {
            int c0 = n0 + warpN * 16 + nt * 8 + (lane & 3) * 2;   // even
            float e0 = accE[mt][nt][0], o0 = accO[mt][nt][0];
            float e1 = accE[mt][nt][1], o1 = accO[mt][nt][1];
            float e2 = accE[mt][nt][2], o2 = accO[mt][nt][2];
            float e3 = accE[mt][nt][3], o3 = accO[mt][nt][3];
            *reinterpret_cast<float2*>(&Out[img + (long)r * N512 + c0]) =
                make_float2(e0 + o0, e1 + o1);
            *reinterpret_cast<float2*>(&Out[img + (long)r * N512 + 510 - c0]) =
                make_float2(e1 - o1, e0 - o0);
            *reinterpret_cast<float2*>(&Out[img + (long)(r + 8) * N512 + c0]) =
                make_float2(e2 + o2, e3 + o3);
            *reinterpret_cast<float2*>(&Out[img + (long)(r + 8) * N512 + 510 - c0]) =
                make_float2(e3 - o3, e2 - o2);
        }
    }
}

// ---------------- host launcher ----------------
extern "C" void kernel_launch(void* const* d_in, const int* in_sizes, int n_in,
                              void* d_out, int out_size) {
    const float* X = (const float*)d_in[0];
    float* out = (float*)d_out;

    __half *pXh, *pDd, *pTte, *pTto, *pTre, *pTro;
    cudaGetSymbolAddress((void**)&pXh,  g_Xh);
    cudaGetSymbolAddress((void**)&pDd,  g_Dd);
    cudaGetSymbolAddress((void**)&pTte, g_Tte);
    cudaGetSymbolAddress((void**)&pTto, g_Tto);
    cudaGetSymbolAddress((void**)&pTre, g_Tre);
    cudaGetSymbolAddress((void**)&pTro, g_Tro);

    cudaFuncSetAttribute(gemm_s1, cudaFuncAttributeMaxDynamicSharedMemorySize, SMEMT);
    cudaFuncSetAttribute(gemm_s2, cudaFuncAttributeMaxDynamicSharedMemorySize, SMEMT);

    build_basis<<<256, 256>>>(pTte, pTto, pTre, pTro);
    quant_X<<<(int)(NELEM / 4 / 256), 256>>>((const float4*)X, (uint2*)pXh);

    dim3 g1(8, 2, NBATCH);   // w-tiles, i-tiles, images
    gemm_s1<<<g1, 256, SMEMT>>>(pXh, pTte, pTto, pDd);

    dim3 g2(4, 4, NBATCH);   // n-tiles, i-tiles, images
    gemm_s2<<<g2, 256, SMEMT>>>(pDd, pTre, pTro, out);
}